// round 1
// baseline (speedup 1.0000x reference)
#include <cuda_runtime.h>
#include <cuda_bf16.h>
#include <cstdint>

// Problem constants
#define BB 2
#define CC 128
#define NN 4096
#define THRESH2 64.0f
#define BN_EPS 1e-5f

// ---------------- scratch (device globals; no allocation allowed) ------------
__device__ float g_xf[BB * NN * CC];          // [b][n][c]  4 MB
__device__ float g_sq[BB * NN];               // row squared norms
__device__ float g_y [BB * NN * CC];          // fc output  4 MB
__device__ unsigned char g_H[(size_t)BB * NN * NN];  // incidence bytes, 32 MB
__device__ float g_E [BB * NN * CC];          // hyperedge means 4 MB
__device__ float g_xe[BB * NN * CC];          // y + x_out 4 MB
__device__ float g_mean[CC];
__device__ float g_rstd[CC];

// ---------------- K1: NCHW -> [b][n][c] transpose ---------------------------
__global__ void transpose_kernel(const float* __restrict__ x) {
    __shared__ float tile[32][33];
    int b = blockIdx.z;
    int c0 = blockIdx.x * 32;
    int n0 = blockIdx.y * 32;
    int tx = threadIdx.x, ty = threadIdx.y;   // (32,8)
    #pragma unroll
    for (int r = 0; r < 32; r += 8)
        tile[ty + r][tx] = x[((size_t)b * CC + c0 + ty + r) * NN + n0 + tx];
    __syncthreads();
    #pragma unroll
    for (int r = 0; r < 32; r += 8)
        g_xf[((size_t)b * NN + n0 + ty + r) * CC + c0 + tx] = tile[tx][ty + r];
}

// ---------------- K1b: per-row squared norm ---------------------------------
__global__ void sq_kernel() {
    int r = blockIdx.x;                        // 0..BB*NN-1
    float v = g_xf[(size_t)r * CC + threadIdx.x];
    float s = v * v;
    #pragma unroll
    for (int o = 16; o > 0; o >>= 1) s += __shfl_xor_sync(0xffffffffu, s, o);
    __shared__ float ws[4];
    if ((threadIdx.x & 31) == 0) ws[threadIdx.x >> 5] = s;
    __syncthreads();
    if (threadIdx.x == 0) g_sq[r] = ws[0] + ws[1] + ws[2] + ws[3];
}

// ---------------- K2: y = xf @ W^T + b  (128-wide, K=128) --------------------
__global__ void gemm_y(const float* __restrict__ Wfc, const float* __restrict__ bfc) {
    int b = blockIdx.z;
    int n0 = blockIdx.x * 128;
    const float* A = g_xf + (size_t)b * NN * CC;
    __shared__ float As[16][128];
    __shared__ float Bs[16][128];
    float acc[8][8];
    #pragma unroll
    for (int i = 0; i < 8; i++)
        #pragma unroll
        for (int j = 0; j < 8; j++) acc[i][j] = 0.f;

    int tid = threadIdx.x;                    // 256 threads
    int tx = tid % 16, ty = tid / 16;
    int arow = tid / 4;                       // 0..63
    int acol = (tid % 4) * 4;                 // 0,4,8,12

    for (int k0 = 0; k0 < CC; k0 += 16) {
        #pragma unroll
        for (int r = 0; r < 2; r++) {
            int row = arow + r * 64;
            float4 v = *(const float4*)(A + (size_t)(n0 + row) * CC + k0 + acol);
            As[acol + 0][row] = v.x; As[acol + 1][row] = v.y;
            As[acol + 2][row] = v.z; As[acol + 3][row] = v.w;
        }
        #pragma unroll
        for (int r = 0; r < 2; r++) {
            int row = arow + r * 64;          // d
            float4 v = *(const float4*)(Wfc + (size_t)row * CC + k0 + acol);
            Bs[acol + 0][row] = v.x; Bs[acol + 1][row] = v.y;
            Bs[acol + 2][row] = v.z; Bs[acol + 3][row] = v.w;
        }
        __syncthreads();
        #pragma unroll
        for (int k = 0; k < 16; k++) {
            float am[8], bn[8];
            #pragma unroll
            for (int i = 0; i < 8; i++) am[i] = As[k][ty * 8 + i];
            #pragma unroll
            for (int j = 0; j < 8; j++) bn[j] = Bs[k][tx * 8 + j];
            #pragma unroll
            for (int i = 0; i < 8; i++)
                #pragma unroll
                for (int j = 0; j < 8; j++) acc[i][j] += am[i] * bn[j];
        }
        __syncthreads();
    }
    float* Y = g_y + (size_t)b * NN * CC;
    #pragma unroll
    for (int i = 0; i < 8; i++) {
        int n = n0 + ty * 8 + i;
        #pragma unroll
        for (int j = 0; j < 8; j++) {
            int d = tx * 8 + j;
            Y[(size_t)n * CC + d] = acc[i][j] + bfc[d];
        }
    }
}

// ---------------- K3: Gram + threshold -> H bytes (symmetric tiles) ----------
__global__ void gemm_H() {
    int b = blockIdx.z;
    int i = blockIdx.y, j = blockIdx.x;
    if (j < i) return;                         // symmetric: only upper tiles
    int n0 = i * 128, m0 = j * 128;
    const float* A = g_xf + (size_t)b * NN * CC;

    __shared__ float As[16][128];
    __shared__ float Bs[16][128];
    __shared__ unsigned char sH[128][128];

    float acc[8][8];
    #pragma unroll
    for (int p = 0; p < 8; p++)
        #pragma unroll
        for (int q = 0; q < 8; q++) acc[p][q] = 0.f;

    int tid = threadIdx.x;
    int tx = tid % 16, ty = tid / 16;
    int arow = tid / 4;
    int acol = (tid % 4) * 4;

    for (int k0 = 0; k0 < CC; k0 += 16) {
        #pragma unroll
        for (int r = 0; r < 2; r++) {
            int row = arow + r * 64;
            float4 v = *(const float4*)(A + (size_t)(n0 + row) * CC + k0 + acol);
            As[acol + 0][row] = v.x; As[acol + 1][row] = v.y;
            As[acol + 2][row] = v.z; As[acol + 3][row] = v.w;
        }
        #pragma unroll
        for (int r = 0; r < 2; r++) {
            int row = arow + r * 64;
            float4 v = *(const float4*)(A + (size_t)(m0 + row) * CC + k0 + acol);
            Bs[acol + 0][row] = v.x; Bs[acol + 1][row] = v.y;
            Bs[acol + 2][row] = v.z; Bs[acol + 3][row] = v.w;
        }
        __syncthreads();
        #pragma unroll
        for (int k = 0; k < 16; k++) {
            float am[8], bn[8];
            #pragma unroll
            for (int p = 0; p < 8; p++) am[p] = As[k][ty * 8 + p];
            #pragma unroll
            for (int q = 0; q < 8; q++) bn[q] = Bs[k][tx * 8 + q];
            #pragma unroll
            for (int p = 0; p < 8; p++)
                #pragma unroll
                for (int q = 0; q < 8; q++) acc[p][q] += am[p] * bn[q];
        }
        __syncthreads();
    }

    // threshold: dist < 8  <=>  sq[n] + sq[m] - 2*dot < 64
    const float* sqb = g_sq + (size_t)b * NN;
    float sn[8], sm[8];
    #pragma unroll
    for (int p = 0; p < 8; p++) sn[p] = sqb[n0 + ty * 8 + p];
    #pragma unroll
    for (int q = 0; q < 8; q++) sm[q] = sqb[m0 + tx * 8 + q];
    #pragma unroll
    for (int p = 0; p < 8; p++)
        #pragma unroll
        for (int q = 0; q < 8; q++) {
            float d2 = sn[p] + sm[q] - 2.0f * acc[p][q];
            sH[ty * 8 + p][tx * 8 + q] = (d2 < THRESH2) ? 1 : 0;
        }
    __syncthreads();

    unsigned char* Hb = g_H + (size_t)b * NN * NN;
    // normal orientation: rows n0..n0+127, cols m0..  (packed uint writes)
    for (int idx = tid; idx < 128 * 32; idx += 256) {
        int row = idx >> 5;
        int word = idx & 31;
        unsigned int v = (unsigned int)sH[row][word * 4 + 0]
                       | ((unsigned int)sH[row][word * 4 + 1] << 8)
                       | ((unsigned int)sH[row][word * 4 + 2] << 16)
                       | ((unsigned int)sH[row][word * 4 + 3] << 24);
        *(unsigned int*)(Hb + (size_t)(n0 + row) * NN + m0 + word * 4) = v;
    }
    if (j > i) {
        for (int idx = tid; idx < 128 * 32; idx += 256) {
            int row = idx >> 5;
            int word = idx & 31;
            unsigned int v = (unsigned int)sH[word * 4 + 0][row]
                           | ((unsigned int)sH[word * 4 + 1][row] << 8)
                           | ((unsigned int)sH[word * 4 + 2][row] << 16)
                           | ((unsigned int)sH[word * 4 + 3][row] << 24);
            *(unsigned int*)(Hb + (size_t)(m0 + row) * NN + n0 + word * 4) = v;
        }
    }
}

// ---------------- K4/K5: normalized aggregation over H rows ------------------
// MODE 0:  E  = (H @ y) / deg
// MODE 1:  xe = y + (H @ E) / deg
template <int MODE>
__global__ void agg_kernel() {
    int b = blockIdx.y;
    int n = blockIdx.x;
    int t = threadIdx.x;                       // 128 threads = channels
    const unsigned char* Hrow = g_H + ((size_t)b * NN + n) * NN;

    __shared__ uint4 sRow[NN / 16];            // 4096 bytes
    sRow[t]        = ((const uint4*)Hrow)[t];
    sRow[t + 128]  = ((const uint4*)Hrow)[t + 128];
    __syncthreads();

    const float* S = (MODE == 0 ? g_y : g_E) + (size_t)b * NN * CC;
    const unsigned long long* sw = (const unsigned long long*)sRow;

    float acc = 0.f;
    int deg = 0;
    #pragma unroll 4
    for (int w = 0; w < NN / 8; w++) {
        unsigned long long hv = sw[w];
        if (hv) {
            int mbase = w * 8;
            #pragma unroll
            for (int q = 0; q < 8; q++) {
                if ((hv >> (q * 8)) & 0xffull) {
                    acc += S[(size_t)(mbase + q) * CC + t];
                    deg++;
                }
            }
        }
    }
    float inv = (deg > 0) ? (1.0f / (float)deg) : 0.0f;
    float v = acc * inv;
    size_t o = ((size_t)b * NN + n) * CC + t;
    if (MODE == 0) g_E[o] = v;
    else           g_xe[o] = g_y[o] + v;
}

// ---------------- K6: per-channel batch stats --------------------------------
__global__ void stats_kernel() {
    int c = blockIdx.x;                        // 128
    float s = 0.f, s2 = 0.f;
    for (int r = threadIdx.x; r < BB * NN; r += 256) {
        float v = g_xe[(size_t)r * CC + c];
        s += v; s2 += v * v;
    }
    #pragma unroll
    for (int o = 16; o > 0; o >>= 1) {
        s  += __shfl_xor_sync(0xffffffffu, s,  o);
        s2 += __shfl_xor_sync(0xffffffffu, s2, o);
    }
    __shared__ float ws[8], ws2[8];
    int wid = threadIdx.x >> 5;
    if ((threadIdx.x & 31) == 0) { ws[wid] = s; ws2[wid] = s2; }
    __syncthreads();
    if (threadIdx.x == 0) {
        float ts = 0.f, ts2 = 0.f;
        #pragma unroll
        for (int k = 0; k < 8; k++) { ts += ws[k]; ts2 += ws2[k]; }
        float mean = ts / (float)(BB * NN);
        float var  = ts2 / (float)(BB * NN) - mean * mean;
        g_mean[c] = mean;
        g_rstd[c] = rsqrtf(var + BN_EPS);
    }
}

// ---------------- K7: BN + SiLU + transpose back to NCHW ---------------------
__global__ void out_kernel(const float* __restrict__ gamma,
                           const float* __restrict__ beta,
                           float* __restrict__ out) {
    __shared__ float tile[32][33];
    int b = blockIdx.z;
    int n0 = blockIdx.x * 32;
    int c0 = blockIdx.y * 32;
    int tx = threadIdx.x, ty = threadIdx.y;    // (32,8)
    #pragma unroll
    for (int r = 0; r < 32; r += 8) {
        int n = n0 + ty + r;
        tile[ty + r][tx] = g_xe[((size_t)b * NN + n) * CC + c0 + tx];
    }
    __syncthreads();
    #pragma unroll
    for (int r = 0; r < 32; r += 8) {
        int c = c0 + ty + r;
        float v = tile[tx][ty + r];            // xe[n0+tx][c]
        float xn = gamma[c] * ((v - g_mean[c]) * g_rstd[c]) + beta[c];
        float sig = 1.0f / (1.0f + expf(-xn));
        out[((size_t)b * CC + c) * NN + n0 + tx] = xn * sig;
    }
}

// ---------------- entry ------------------------------------------------------
extern "C" void kernel_launch(void* const* d_in, const int* in_sizes, int n_in,
                              void* d_out, int out_size) {
    const float* x     = (const float*)d_in[0];
    const float* Wfc   = (const float*)d_in[1];
    const float* bfc   = (const float*)d_in[2];
    const float* gamma = (const float*)d_in[3];
    const float* beta  = (const float*)d_in[4];
    float* out = (float*)d_out;

    dim3 tb(32, 8);
    transpose_kernel<<<dim3(CC / 32, NN / 32, BB), tb>>>(x);
    sq_kernel<<<BB * NN, 128>>>();
    gemm_y<<<dim3(NN / 128, 1, BB), 256>>>(Wfc, bfc);
    gemm_H<<<dim3(NN / 128, NN / 128, BB), 256>>>();
    agg_kernel<0><<<dim3(NN, BB), 128>>>();
    agg_kernel<1><<<dim3(NN, BB), 128>>>();
    stats_kernel<<<CC, 256>>>();
    out_kernel<<<dim3(NN / 32, CC / 32, BB), tb>>>(gamma, beta, out);
}

// round 3
// speedup vs baseline: 3.8293x; 3.8293x over previous
#include <cuda_runtime.h>
#include <cuda_bf16.h>
#include <cstdint>

#define BB 2
#define CC 128
#define NN 4096
#define THRESH2 64.0f
#define BN_EPS 1e-5f

// ---------------- scratch (device globals) -----------------------------------
__device__ float g_xf[BB * NN * CC];                  // [b][n][c] fp32, 4 MB
__device__ __nv_bfloat16 g_xb[BB * NN * CC];          // bf16 copy, 2 MB
__device__ float g_sq[BB * NN];
__device__ float g_y [BB * NN * CC];
__device__ unsigned int g_Hb[(size_t)BB * NN * (NN / 32)];  // bit mask, 4 MB
__device__ float g_E [BB * NN * CC];
__device__ float g_xe[BB * NN * CC];
__device__ float g_part[64][2][CC];
__device__ float g_mean[CC];
__device__ float g_rstd[CC];

__device__ __forceinline__ uint32_t smem_u32(const void* p) {
    uint32_t a;
    asm("{ .reg .u64 t; cvta.to.shared.u64 t, %1; cvt.u32.u64 %0, t; }" : "=r"(a) : "l"(p));
    return a;
}

// ---------------- K1: NCHW -> [b][n][c] transpose (+bf16 copy) ---------------
__global__ void transpose_kernel(const float* __restrict__ x) {
    __shared__ float tile[32][33];
    int b = blockIdx.z;
    int c0 = blockIdx.x * 32;
    int n0 = blockIdx.y * 32;
    int tx = threadIdx.x, ty = threadIdx.y;
    #pragma unroll
    for (int r = 0; r < 32; r += 8)
        tile[ty + r][tx] = x[((size_t)b * CC + c0 + ty + r) * NN + n0 + tx];
    __syncthreads();
    #pragma unroll
    for (int r = 0; r < 32; r += 8) {
        float v = tile[tx][ty + r];
        size_t o = ((size_t)b * NN + n0 + ty + r) * CC + c0 + tx;
        g_xf[o] = v;
        g_xb[o] = __float2bfloat16(v);
    }
}

// ---------------- K1b: row squared norms -------------------------------------
__global__ void sq_kernel() {
    int r = blockIdx.x;
    float v = g_xf[(size_t)r * CC + threadIdx.x];
    float s = v * v;
    #pragma unroll
    for (int o = 16; o > 0; o >>= 1) s += __shfl_xor_sync(0xffffffffu, s, o);
    __shared__ float ws[4];
    if ((threadIdx.x & 31) == 0) ws[threadIdx.x >> 5] = s;
    __syncthreads();
    if (threadIdx.x == 0) g_sq[r] = ws[0] + ws[1] + ws[2] + ws[3];
}

// ---------------- K2: y = xf @ W^T + b  (64x128 tiles, fp32 SIMT) -----------
__global__ void gemm_y(const float* __restrict__ Wfc, const float* __restrict__ bfc) {
    int b = blockIdx.z;
    int n0 = blockIdx.x * 64;
    const float* A = g_xf + (size_t)b * NN * CC;
    __shared__ float As[16][64];
    __shared__ float Bs[16][128];
    float acc[4][8];
    #pragma unroll
    for (int i = 0; i < 4; i++)
        #pragma unroll
        for (int j = 0; j < 8; j++) acc[i][j] = 0.f;

    int tid = threadIdx.x;
    int tx = tid % 16, ty = tid / 16;
    int lrow = tid >> 2;
    int lcol = (tid & 3) * 4;

    for (int k0 = 0; k0 < CC; k0 += 16) {
        {
            float4 v = *(const float4*)(A + (size_t)(n0 + lrow) * CC + k0 + lcol);
            As[lcol + 0][lrow] = v.x; As[lcol + 1][lrow] = v.y;
            As[lcol + 2][lrow] = v.z; As[lcol + 3][lrow] = v.w;
        }
        #pragma unroll
        for (int r = 0; r < 2; r++) {
            int row = lrow + r * 64;
            float4 v = *(const float4*)(Wfc + (size_t)row * CC + k0 + lcol);
            Bs[lcol + 0][row] = v.x; Bs[lcol + 1][row] = v.y;
            Bs[lcol + 2][row] = v.z; Bs[lcol + 3][row] = v.w;
        }
        __syncthreads();
        #pragma unroll
        for (int k = 0; k < 16; k++) {
            float am[4], bn[8];
            #pragma unroll
            for (int i = 0; i < 4; i++) am[i] = As[k][ty * 4 + i];
            #pragma unroll
            for (int j = 0; j < 8; j++) bn[j] = Bs[k][tx * 8 + j];
            #pragma unroll
            for (int i = 0; i < 4; i++)
                #pragma unroll
                for (int j = 0; j < 8; j++) acc[i][j] += am[i] * bn[j];
        }
        __syncthreads();
    }
    float* Y = g_y + (size_t)b * NN * CC;
    #pragma unroll
    for (int i = 0; i < 4; i++) {
        int n = n0 + ty * 4 + i;
        #pragma unroll
        for (int j = 0; j < 8; j++) {
            int d = tx * 8 + j;
            Y[(size_t)n * CC + d] = acc[i][j] + bfc[d];
        }
    }
}

// ---------------- K3: HMMA (mma.sync bf16) Gram + threshold -> bit mask ------
// dynamic smem layout:
//   sqI @ 0      (512 B)
//   sqJ @ 512    (512 B)
//   A   @ 1024   (32 KB)  128 rows x 256 B, 16B-chunk XOR swizzle
//   B   @ 33792  (32 KB)
//   H   @ 66560  (16 KB)  byte tile 128x128
#define HS_SQI 0
#define HS_SQJ 512
#define HS_A   1024
#define HS_B   33792
#define HS_H   66560
#define HS_TOTAL (66560 + 16384)

__device__ __forceinline__ void ldm_x4(uint32_t a[4], uint32_t addr) {
    asm volatile("ldmatrix.sync.aligned.m8n8.x4.shared.b16 {%0,%1,%2,%3}, [%4];"
                 : "=r"(a[0]), "=r"(a[1]), "=r"(a[2]), "=r"(a[3]) : "r"(addr));
}
__device__ __forceinline__ void ldm_x2(uint32_t b[2], uint32_t addr) {
    asm volatile("ldmatrix.sync.aligned.m8n8.x2.shared.b16 {%0,%1}, [%2];"
                 : "=r"(b[0]), "=r"(b[1]) : "r"(addr));
}
__device__ __forceinline__ void mma16816(float c[4], const uint32_t a[4], const uint32_t b[2]) {
    asm volatile(
        "mma.sync.aligned.m16n8k16.row.col.f32.bf16.bf16.f32 "
        "{%0,%1,%2,%3}, {%4,%5,%6,%7}, {%8,%9}, {%0,%1,%2,%3};"
        : "+f"(c[0]), "+f"(c[1]), "+f"(c[2]), "+f"(c[3])
        : "r"(a[0]), "r"(a[1]), "r"(a[2]), "r"(a[3]), "r"(b[0]), "r"(b[1]));
}

__global__ void __launch_bounds__(256, 2) gemm_H_mma() {
    extern __shared__ char smem[];
    int tid = threadIdx.x;
    int wid = tid >> 5, lane = tid & 31;
    int b = blockIdx.y;

    // triangular decode: blockIdx.x in [0,528) -> (ti <= tj)
    int idx = blockIdx.x, ti = 0, rem = 32;
    while (idx >= rem) { idx -= rem; ti++; rem--; }
    int tj = ti + idx;
    int n0 = ti * 128, m0 = tj * 128;

    float* sSqI = (float*)(smem + HS_SQI);
    float* sSqJ = (float*)(smem + HS_SQJ);
    if (tid < 128) {
        sSqI[tid] = g_sq[(size_t)b * NN + n0 + tid];
        sSqJ[tid] = g_sq[(size_t)b * NN + m0 + tid];
    }

    // load tiles: 128 rows x 16 chunks(16B). chunk c stored at c ^ (row & 7)
    {
        const uint4* Ag = (const uint4*)(g_xb + ((size_t)b * NN + n0) * CC);
        const uint4* Bg = (const uint4*)(g_xb + ((size_t)b * NN + m0) * CC);
        #pragma unroll
        for (int it = 0; it < 8; it++) {
            int id = tid + it * 256;           // 0..2047
            int row = id >> 4, ch = id & 15;
            int sw = (ch ^ (row & 7));
            *(uint4*)(smem + HS_A + row * 256 + sw * 16) = Ag[(size_t)row * 16 + ch];
            *(uint4*)(smem + HS_B + row * 256 + sw * 16) = Bg[(size_t)row * 16 + ch];
        }
    }
    __syncthreads();

    // warp tile: 32 (m) x 64 (n).  warp_m = wid & 3, warp_n = wid >> 2
    int warp_m = wid & 3, warp_n = wid >> 2;
    int mbase = warp_m * 32;                   // row offset in A tile
    int nbase = warp_n * 64;                   // row offset in B tile

    float acc[2][8][4];
    #pragma unroll
    for (int mt = 0; mt < 2; mt++)
        #pragma unroll
        for (int nt = 0; nt < 8; nt++)
            #pragma unroll
            for (int q = 0; q < 4; q++) acc[mt][nt][q] = 0.f;

    uint32_t Abase = smem_u32(smem + HS_A);
    uint32_t Bbase = smem_u32(smem + HS_B);

    // per-lane ldmatrix row indices
    int a_row_local = lane & 15;               // 0..15
    int a_hi = lane >> 4;                      // 0: k-low chunk, 1: k-high
    int b_row_local = lane & 7;
    int b_hi = (lane >> 3) & 1;

    #pragma unroll
    for (int kk = 0; kk < 8; kk++) {
        uint32_t afr[2][4];
        #pragma unroll
        for (int mt = 0; mt < 2; mt++) {
            int row = mbase + mt * 16 + a_row_local;
            int ch = (2 * kk + a_hi) ^ (row & 7);
            ldm_x4(afr[mt], Abase + row * 256 + ch * 16);
        }
        uint32_t bfr[8][2];
        #pragma unroll
        for (int nt = 0; nt < 8; nt++) {
            int row = nbase + nt * 8 + b_row_local;
            int ch = (2 * kk + b_hi) ^ (row & 7);
            ldm_x2(bfr[nt], Bbase + row * 256 + ch * 16);
        }
        #pragma unroll
        for (int mt = 0; mt < 2; mt++)
            #pragma unroll
            for (int nt = 0; nt < 8; nt++)
                mma16816(acc[mt][nt], afr[mt], bfr[nt]);
    }

    // epilogue: threshold into byte tile
    unsigned char* sH = (unsigned char*)(smem + HS_H);
    int rrow = lane >> 2;                      // 0..7
    int ccol = (lane & 3) * 2;
    #pragma unroll
    for (int mt = 0; mt < 2; mt++) {
        #pragma unroll
        for (int nt = 0; nt < 8; nt++) {
            int col = nbase + nt * 8 + ccol;
            float sm0 = sSqJ[col], sm1 = sSqJ[col + 1];
            #pragma unroll
            for (int h = 0; h < 2; h++) {
                int row = mbase + mt * 16 + rrow + h * 8;
                float sqn = sSqI[row];
                float d20 = sqn + sm0 - 2.0f * acc[mt][nt][h * 2 + 0];
                float d21 = sqn + sm1 - 2.0f * acc[mt][nt][h * 2 + 1];
                sH[row * 128 + col]     = (d20 < THRESH2) ? 1 : 0;
                sH[row * 128 + col + 1] = (d21 < THRESH2) ? 1 : 0;
            }
        }
    }
    __syncthreads();

    // pack bits, normal orientation: 128 rows x 4 words
    unsigned int* Hb = g_Hb + (size_t)b * NN * (NN / 32);
    #pragma unroll
    for (int it = 0; it < 2; it++) {
        int id = tid + it * 256;               // 0..511
        int row = id >> 2, w = id & 3;
        const unsigned int* src = (const unsigned int*)(sH + row * 128 + w * 32);
        unsigned int bits = 0;
        #pragma unroll
        for (int k = 0; k < 8; k++) {
            unsigned int u = src[k];
            bits |= (u & 1u) << (k * 4);
            bits |= ((u >> 8) & 1u) << (k * 4 + 1);
            bits |= ((u >> 16) & 1u) << (k * 4 + 2);
            bits |= ((u >> 24) & 1u) << (k * 4 + 3);
        }
        Hb[(size_t)(n0 + row) * (NN / 32) + (m0 >> 5) + w] = bits;
    }
    // transposed orientation for off-diagonal tiles
    if (ti != tj) {
        #pragma unroll
        for (int it = 0; it < 2; it++) {
            int id = tid + it * 256;
            int mrow = id & 127, w = id >> 7;  // mrow varies across threads -> coalesced-ish smem
            unsigned int bits = 0;
            #pragma unroll
            for (int q = 0; q < 32; q++)
                bits |= (unsigned int)(sH[(w * 32 + q) * 128 + mrow] & 1u) << q;
            Hb[(size_t)(m0 + mrow) * (NN / 32) + (n0 >> 5) + w] = bits;
        }
    }
}

// ---------------- K4/K5: normalized aggregation over H bit rows --------------
template <int MODE>
__global__ void agg_kernel() {
    int b = blockIdx.y;
    int n = blockIdx.x;
    int t = threadIdx.x;                       // 128 = channels
    __shared__ unsigned int sW[NN / 32];
    sW[t] = g_Hb[((size_t)b * NN + n) * (NN / 32) + t];
    __syncthreads();

    const float* S = (MODE == 0 ? g_y : g_E) + (size_t)b * NN * CC;
    float acc = 0.f;
    int deg = 0;
    #pragma unroll 4
    for (int w = 0; w < NN / 32; w++) {
        unsigned int wv = sW[w];
        while (wv) {
            int q = __ffs(wv) - 1;
            wv &= wv - 1;
            acc += S[(size_t)(w * 32 + q) * CC + t];
            deg++;
        }
    }
    float inv = (deg > 0) ? (1.0f / (float)deg) : 0.0f;
    float v = acc * inv;
    size_t o = ((size_t)b * NN + n) * CC + t;
    if (MODE == 0) g_E[o] = v;
    else           g_xe[o] = g_y[o] + v;
}

// ---------------- K6: batch stats (two-phase, coalesced) ---------------------
__global__ void stats_p1() {
    int tid = threadIdx.x;                     // 256
    int c = tid & 127, h = tid >> 7;
    int r0 = blockIdx.x * 128;
    float s = 0.f, s2 = 0.f;
    for (int r = r0 + h; r < r0 + 128; r += 2) {
        float v = g_xe[(size_t)r * CC + c];
        s += v; s2 += v * v;
    }
    __shared__ float sS[2][CC], sS2[2][CC];
    sS[h][c] = s; sS2[h][c] = s2;
    __syncthreads();
    if (tid < CC) {
        g_part[blockIdx.x][0][tid] = sS[0][tid] + sS[1][tid];
        g_part[blockIdx.x][1][tid] = sS2[0][tid] + sS2[1][tid];
    }
}
__global__ void stats_p2() {
    int c = threadIdx.x;
    float s = 0.f, s2 = 0.f;
    #pragma unroll 8
    for (int k = 0; k < 64; k++) { s += g_part[k][0][c]; s2 += g_part[k][1][c]; }
    float mean = s / (float)(BB * NN);
    float var = s2 / (float)(BB * NN) - mean * mean;
    g_mean[c] = mean;
    g_rstd[c] = rsqrtf(var + BN_EPS);
}

// ---------------- K7: BN + SiLU + transpose back to NCHW ---------------------
__global__ void out_kernel(const float* __restrict__ gamma,
                           const float* __restrict__ beta,
                           float* __restrict__ out) {
    __shared__ float tile[32][33];
    int b = blockIdx.z;
    int n0 = blockIdx.x * 32;
    int c0 = blockIdx.y * 32;
    int tx = threadIdx.x, ty = threadIdx.y;
    #pragma unroll
    for (int r = 0; r < 32; r += 8)
        tile[ty + r][tx] = g_xe[((size_t)b * NN + n0 + ty + r) * CC + c0 + tx];
    __syncthreads();
    #pragma unroll
    for (int r = 0; r < 32; r += 8) {
        int c = c0 + ty + r;
        float v = tile[tx][ty + r];
        float xn = gamma[c] * ((v - g_mean[c]) * g_rstd[c]) + beta[c];
        float sig = 1.0f / (1.0f + expf(-xn));
        out[((size_t)b * CC + c) * NN + n0 + tx] = xn * sig;
    }
}

// ---------------- entry ------------------------------------------------------
extern "C" void kernel_launch(void* const* d_in, const int* in_sizes, int n_in,
                              void* d_out, int out_size) {
    const float* x     = (const float*)d_in[0];
    const float* Wfc   = (const float*)d_in[1];
    const float* bfc   = (const float*)d_in[2];
    const float* gamma = (const float*)d_in[3];
    const float* beta  = (const float*)d_in[4];
    float* out = (float*)d_out;

    cudaFuncSetAttribute(gemm_H_mma, cudaFuncAttributeMaxDynamicSharedMemorySize,
                         HS_TOTAL);

    dim3 tb(32, 8);
    transpose_kernel<<<dim3(CC / 32, NN / 32, BB), tb>>>(x);
    sq_kernel<<<BB * NN, 128>>>();
    gemm_y<<<dim3(NN / 64, 1, BB), 256>>>(Wfc, bfc);
    gemm_H_mma<<<dim3(528, BB), 256, HS_TOTAL>>>();
    agg_kernel<0><<<dim3(NN, BB), 128>>>();
    agg_kernel<1><<<dim3(NN, BB), 128>>>();
    stats_p1<<<64, 256>>>();
    stats_p2<<<1, 128>>>();
    out_kernel<<<dim3(NN / 32, CC / 32, BB), tb>>>(gamma, beta, out);
}

// round 4
// speedup vs baseline: 4.6241x; 1.2076x over previous
#include <cuda_runtime.h>
#include <cuda_bf16.h>
#include <cstdint>

#define BB 2
#define CC 128
#define NN 4096
#define THRESH2 64.0f
#define BN_EPS 1e-5f

// ---------------- scratch (device globals) -----------------------------------
__device__ __nv_bfloat16 g_xb[BB * NN * CC];          // hi split, 2 MB
__device__ __nv_bfloat16 g_xl[BB * NN * CC];          // lo split, 2 MB
__device__ __nv_bfloat16 g_Whi[CC * CC];
__device__ __nv_bfloat16 g_Wlo[CC * CC];
__device__ float g_sq[BB * NN];
__device__ float g_y [BB * NN * CC];
__device__ unsigned int g_Hb[(size_t)BB * NN * (NN / 32)];  // bit mask, 4 MB
__device__ float g_E [BB * NN * CC];
__device__ float g_xe[BB * NN * CC];
__device__ float g_part[64][2][CC];
__device__ float g_mean[CC];
__device__ float g_rstd[CC];

__device__ __forceinline__ uint32_t smem_u32(const void* p) {
    uint32_t a;
    asm("{ .reg .u64 t; cvta.to.shared.u64 t, %1; cvt.u32.u64 %0, t; }" : "=r"(a) : "l"(p));
    return a;
}
__device__ __forceinline__ void ldm_x4(uint32_t a[4], uint32_t addr) {
    asm volatile("ldmatrix.sync.aligned.m8n8.x4.shared.b16 {%0,%1,%2,%3}, [%4];"
                 : "=r"(a[0]), "=r"(a[1]), "=r"(a[2]), "=r"(a[3]) : "r"(addr));
}
__device__ __forceinline__ void mma16816(float c[4], const uint32_t a[4], const uint32_t b[2]) {
    asm volatile(
        "mma.sync.aligned.m16n8k16.row.col.f32.bf16.bf16.f32 "
        "{%0,%1,%2,%3}, {%4,%5,%6,%7}, {%8,%9}, {%0,%1,%2,%3};"
        : "+f"(c[0]), "+f"(c[1]), "+f"(c[2]), "+f"(c[3])
        : "r"(a[0]), "r"(a[1]), "r"(a[2]), "r"(a[3]), "r"(b[0]), "r"(b[1]));
}

// ---------------- K0: W hi/lo split ------------------------------------------
__global__ void wprep_kernel(const float* __restrict__ Wfc) {
    int i = blockIdx.x * blockDim.x + threadIdx.x;   // 16384
    float v = Wfc[i];
    __nv_bfloat16 h = __float2bfloat16(v);
    g_Whi[i] = h;
    g_Wlo[i] = __float2bfloat16(v - __bfloat162float(h));
}

// ---------------- K1: NCHW -> [b][n][c] hi/lo split + sq ---------------------
__global__ void transpose_kernel(const float* __restrict__ x) {
    __shared__ float tile[32][33];
    int b = blockIdx.z;
    int c0 = blockIdx.x * 32;
    int n0 = blockIdx.y * 32;
    int tx = threadIdx.x, ty = threadIdx.y;
    #pragma unroll
    for (int r = 0; r < 32; r += 8)
        tile[ty + r][tx] = x[((size_t)b * CC + c0 + ty + r) * NN + n0 + tx];
    __syncthreads();
    #pragma unroll
    for (int r = 0; r < 32; r += 8) {
        float v = tile[tx][ty + r];
        size_t o = ((size_t)b * NN + n0 + ty + r) * CC + c0 + tx;
        __nv_bfloat16 h = __float2bfloat16(v);
        g_xb[o] = h;
        g_xl[o] = __float2bfloat16(v - __bfloat162float(h));
        float s = v * v;
        #pragma unroll
        for (int o2 = 16; o2 > 0; o2 >>= 1) s += __shfl_xor_sync(0xffffffffu, s, o2);
        if (tx == 0) atomicAdd(&g_sq[(size_t)b * NN + n0 + ty + r], s);
    }
}

// ---------------- K2: y = xf @ W^T + b  (split-bf16 HMMA) --------------------
// smem: Ahi@0 Alo@32K Whi@64K Wlo@96K, each 128x256B swizzled
#define YS_AH 0
#define YS_AL 32768
#define YS_WH 65536
#define YS_WL 98304
#define YS_TOTAL 131072

__global__ void __launch_bounds__(256, 1) gemm_y_mma(const float* __restrict__ bfc) {
    extern __shared__ char smem[];
    int tid = threadIdx.x;
    int wid = tid >> 5, lane = tid & 31;
    int b = blockIdx.y;
    int n0 = blockIdx.x * 128;

    {
        const uint4* Ah = (const uint4*)(g_xb + ((size_t)b * NN + n0) * CC);
        const uint4* Al = (const uint4*)(g_xl + ((size_t)b * NN + n0) * CC);
        const uint4* Wh = (const uint4*)g_Whi;
        const uint4* Wl = (const uint4*)g_Wlo;
        #pragma unroll
        for (int it = 0; it < 8; it++) {
            int id = tid + it * 256;
            int row = id >> 4, ch = id & 15;
            int off = row * 256 + (ch ^ (row & 7)) * 16;
            *(uint4*)(smem + YS_AH + off) = Ah[(size_t)row * 16 + ch];
            *(uint4*)(smem + YS_AL + off) = Al[(size_t)row * 16 + ch];
            *(uint4*)(smem + YS_WH + off) = Wh[(size_t)row * 16 + ch];
            *(uint4*)(smem + YS_WL + off) = Wl[(size_t)row * 16 + ch];
        }
    }
    __syncthreads();

    int warp_m = wid & 3, warp_n = wid >> 2;
    int mbase = warp_m * 32, nbase = warp_n * 64;

    float acc[2][8][4];
    #pragma unroll
    for (int mt = 0; mt < 2; mt++)
        #pragma unroll
        for (int nt = 0; nt < 8; nt++)
            #pragma unroll
            for (int q = 0; q < 4; q++) acc[mt][nt][q] = 0.f;

    int a_row_local = lane & 15;
    int a_hi = lane >> 4;
    int bg = lane >> 3;
    int b_row_local = lane & 7;
    int b_nt_off = bg >> 1;
    int b_hi = bg & 1;

    #pragma unroll
    for (int pass = 0; pass < 3; pass++) {
        uint32_t Abase = smem_u32(smem + (pass == 2 ? YS_AL : YS_AH));
        uint32_t Bbase = smem_u32(smem + (pass == 1 ? YS_WL : YS_WH));
        #pragma unroll
        for (int kk = 0; kk < 8; kk++) {
            uint32_t afr[2][4];
            #pragma unroll
            for (int mt = 0; mt < 2; mt++) {
                int row = mbase + mt * 16 + a_row_local;
                int ch = (2 * kk + a_hi) ^ (row & 7);
                ldm_x4(afr[mt], Abase + row * 256 + ch * 16);
            }
            uint32_t bfr[8][2];
            #pragma unroll
            for (int nt2 = 0; nt2 < 4; nt2++) {
                int row = nbase + nt2 * 16 + b_nt_off * 8 + b_row_local;
                int ch = (2 * kk + b_hi) ^ (row & 7);
                uint32_t r4[4];
                ldm_x4(r4, Bbase + row * 256 + ch * 16);
                bfr[nt2 * 2][0] = r4[0]; bfr[nt2 * 2][1] = r4[1];
                bfr[nt2 * 2 + 1][0] = r4[2]; bfr[nt2 * 2 + 1][1] = r4[3];
            }
            #pragma unroll
            for (int mt = 0; mt < 2; mt++)
                #pragma unroll
                for (int nt = 0; nt < 8; nt++)
                    mma16816(acc[mt][nt], afr[mt], bfr[nt]);
        }
    }

    // epilogue: +bias, write fp32
    int rrow = lane >> 2;
    int ccol = (lane & 3) * 2;
    float* Y = g_y + ((size_t)b * NN + n0) * CC;
    #pragma unroll
    for (int mt = 0; mt < 2; mt++) {
        #pragma unroll
        for (int nt = 0; nt < 8; nt++) {
            int col = nbase + nt * 8 + ccol;
            float b0 = bfc[col], b1 = bfc[col + 1];
            #pragma unroll
            for (int h = 0; h < 2; h++) {
                int row = mbase + mt * 16 + rrow + h * 8;
                Y[(size_t)row * CC + col]     = acc[mt][nt][h * 2 + 0] + b0;
                Y[(size_t)row * CC + col + 1] = acc[mt][nt][h * 2 + 1] + b1;
            }
        }
    }
}

// ---------------- K3: HMMA Gram + threshold -> bit mask ----------------------
#define HS_SQI 0
#define HS_SQJ 512
#define HS_A   1024
#define HS_B   33792
#define HS_H   66560
#define SH_STRIDE 144
#define HS_TOTAL (66560 + 128 * SH_STRIDE)

__global__ void __launch_bounds__(256, 2) gemm_H_mma() {
    extern __shared__ char smem[];
    int tid = threadIdx.x;
    int wid = tid >> 5, lane = tid & 31;
    int b = blockIdx.y;

    int idx = blockIdx.x, ti = 0, rem = 32;
    while (idx >= rem) { idx -= rem; ti++; rem--; }
    int tj = ti + idx;
    int n0 = ti * 128, m0 = tj * 128;

    float* sSqI = (float*)(smem + HS_SQI);
    float* sSqJ = (float*)(smem + HS_SQJ);
    if (tid < 128) {
        sSqI[tid] = g_sq[(size_t)b * NN + n0 + tid];
        sSqJ[tid] = g_sq[(size_t)b * NN + m0 + tid];
    }

    {
        const uint4* Ag = (const uint4*)(g_xb + ((size_t)b * NN + n0) * CC);
        const uint4* Bg = (const uint4*)(g_xb + ((size_t)b * NN + m0) * CC);
        #pragma unroll
        for (int it = 0; it < 8; it++) {
            int id = tid + it * 256;
            int row = id >> 4, ch = id & 15;
            int off = row * 256 + (ch ^ (row & 7)) * 16;
            *(uint4*)(smem + HS_A + off) = Ag[(size_t)row * 16 + ch];
            *(uint4*)(smem + HS_B + off) = Bg[(size_t)row * 16 + ch];
        }
    }
    __syncthreads();

    int warp_m = wid & 3, warp_n = wid >> 2;
    int mbase = warp_m * 32, nbase = warp_n * 64;

    float acc[2][8][4];
    #pragma unroll
    for (int mt = 0; mt < 2; mt++)
        #pragma unroll
        for (int nt = 0; nt < 8; nt++)
            #pragma unroll
            for (int q = 0; q < 4; q++) acc[mt][nt][q] = 0.f;

    uint32_t Abase = smem_u32(smem + HS_A);
    uint32_t Bbase = smem_u32(smem + HS_B);

    int a_row_local = lane & 15;
    int a_hi = lane >> 4;
    int bg = lane >> 3;
    int b_row_local = lane & 7;
    int b_nt_off = bg >> 1;
    int b_hi = bg & 1;

    #pragma unroll
    for (int kk = 0; kk < 8; kk++) {
        uint32_t afr[2][4];
        #pragma unroll
        for (int mt = 0; mt < 2; mt++) {
            int row = mbase + mt * 16 + a_row_local;
            int ch = (2 * kk + a_hi) ^ (row & 7);
            ldm_x4(afr[mt], Abase + row * 256 + ch * 16);
        }
        uint32_t bfr[8][2];
        #pragma unroll
        for (int nt2 = 0; nt2 < 4; nt2++) {
            int row = nbase + nt2 * 16 + b_nt_off * 8 + b_row_local;
            int ch = (2 * kk + b_hi) ^ (row & 7);
            uint32_t r4[4];
            ldm_x4(r4, Bbase + row * 256 + ch * 16);
            bfr[nt2 * 2][0] = r4[0]; bfr[nt2 * 2][1] = r4[1];
            bfr[nt2 * 2 + 1][0] = r4[2]; bfr[nt2 * 2 + 1][1] = r4[3];
        }
        #pragma unroll
        for (int mt = 0; mt < 2; mt++)
            #pragma unroll
            for (int nt = 0; nt < 8; nt++)
                mma16816(acc[mt][nt], afr[mt], bfr[nt]);
    }

    // threshold into padded byte tile
    unsigned char* sH = (unsigned char*)(smem + HS_H);
    int rrow = lane >> 2;
    int ccol = (lane & 3) * 2;
    #pragma unroll
    for (int mt = 0; mt < 2; mt++) {
        #pragma unroll
        for (int nt = 0; nt < 8; nt++) {
            int col = nbase + nt * 8 + ccol;
            float sm0 = sSqJ[col], sm1 = sSqJ[col + 1];
            #pragma unroll
            for (int h = 0; h < 2; h++) {
                int row = mbase + mt * 16 + rrow + h * 8;
                float sqn = sSqI[row];
                float d20 = sqn + sm0 - 2.0f * acc[mt][nt][h * 2 + 0];
                float d21 = sqn + sm1 - 2.0f * acc[mt][nt][h * 2 + 1];
                sH[row * SH_STRIDE + col]     = (d20 < THRESH2) ? 1 : 0;
                sH[row * SH_STRIDE + col + 1] = (d21 < THRESH2) ? 1 : 0;
            }
        }
    }
    __syncthreads();

    unsigned int* Hb = g_Hb + (size_t)b * NN * (NN / 32);
    #pragma unroll
    for (int it = 0; it < 2; it++) {
        int id = tid + it * 256;
        int row = id >> 2, w = id & 3;
        const unsigned int* src = (const unsigned int*)(sH + row * SH_STRIDE + w * 32);
        unsigned int bits = 0;
        #pragma unroll
        for (int k = 0; k < 8; k++) {
            unsigned int u = src[k];
            bits |= (u & 1u) << (k * 4);
            bits |= ((u >> 8) & 1u) << (k * 4 + 1);
            bits |= ((u >> 16) & 1u) << (k * 4 + 2);
            bits |= ((u >> 24) & 1u) << (k * 4 + 3);
        }
        Hb[(size_t)(n0 + row) * (NN / 32) + (m0 >> 5) + w] = bits;
    }
    if (ti != tj) {
        if (tid < 128) {
            int mrow = tid;
            unsigned int wbits[4];
            #pragma unroll
            for (int w = 0; w < 4; w++) {
                unsigned int bits = 0;
                #pragma unroll
                for (int q = 0; q < 32; q++)
                    bits |= (unsigned int)(sH[(w * 32 + q) * SH_STRIDE + mrow] & 1u) << q;
                wbits[w] = bits;
            }
            *(uint4*)&Hb[(size_t)(m0 + mrow) * (NN / 32) + (n0 >> 5)] =
                make_uint4(wbits[0], wbits[1], wbits[2], wbits[3]);
        }
    }
}

// ---------------- K4/K5: normalized aggregation over H bit rows --------------
template <int MODE>
__global__ void agg_kernel() {
    int b = blockIdx.y;
    int n = blockIdx.x;
    int t = threadIdx.x;                       // 128 = channels
    __shared__ unsigned int sW[NN / 32];
    sW[t] = g_Hb[((size_t)b * NN + n) * (NN / 32) + t];
    __syncthreads();

    const float* S = (MODE == 0 ? g_y : g_E) + (size_t)b * NN * CC;
    float acc = 0.f;
    int deg = 0;
    #pragma unroll 4
    for (int w = 0; w < NN / 32; w++) {
        unsigned int wv = sW[w];
        while (wv) {
            int q = __ffs(wv) - 1;
            wv &= wv - 1;
            acc += S[(size_t)(w * 32 + q) * CC + t];
            deg++;
        }
    }
    float inv = (deg > 0) ? (1.0f / (float)deg) : 0.0f;
    float v = acc * inv;
    size_t o = ((size_t)b * NN + n) * CC + t;
    if (MODE == 0) g_E[o] = v;
    else           g_xe[o] = g_y[o] + v;
}

// ---------------- K6: batch stats --------------------------------------------
__global__ void stats_p1() {
    int tid = threadIdx.x;
    int c = tid & 127, h = tid >> 7;
    int r0 = blockIdx.x * 128;
    float s = 0.f, s2 = 0.f;
    for (int r = r0 + h; r < r0 + 128; r += 2) {
        float v = g_xe[(size_t)r * CC + c];
        s += v; s2 += v * v;
    }
    __shared__ float sS[2][CC], sS2[2][CC];
    sS[h][c] = s; sS2[h][c] = s2;
    __syncthreads();
    if (tid < CC) {
        g_part[blockIdx.x][0][tid] = sS[0][tid] + sS[1][tid];
        g_part[blockIdx.x][1][tid] = sS2[0][tid] + sS2[1][tid];
    }
}
__global__ void stats_p2() {
    int c = threadIdx.x;
    float s = 0.f, s2 = 0.f;
    #pragma unroll 8
    for (int k = 0; k < 64; k++) { s += g_part[k][0][c]; s2 += g_part[k][1][c]; }
    float mean = s / (float)(BB * NN);
    float var = s2 / (float)(BB * NN) - mean * mean;
    g_mean[c] = mean;
    g_rstd[c] = rsqrtf(var + BN_EPS);
}

// ---------------- K7: BN + SiLU + transpose back to NCHW ---------------------
__global__ void out_kernel(const float* __restrict__ gamma,
                           const float* __restrict__ beta,
                           float* __restrict__ out) {
    __shared__ float tile[32][33];
    int b = blockIdx.z;
    int n0 = blockIdx.x * 32;
    int c0 = blockIdx.y * 32;
    int tx = threadIdx.x, ty = threadIdx.y;
    #pragma unroll
    for (int r = 0; r < 32; r += 8)
        tile[ty + r][tx] = g_xe[((size_t)b * NN + n0 + ty + r) * CC + c0 + tx];
    __syncthreads();
    #pragma unroll
    for (int r = 0; r < 32; r += 8) {
        int c = c0 + ty + r;
        float v = tile[tx][ty + r];
        float xn = gamma[c] * ((v - g_mean[c]) * g_rstd[c]) + beta[c];
        float sig = 1.0f / (1.0f + expf(-xn));
        out[((size_t)b * CC + c) * NN + n0 + tx] = xn * sig;
    }
}

// ---------------- entry ------------------------------------------------------
extern "C" void kernel_launch(void* const* d_in, const int* in_sizes, int n_in,
                              void* d_out, int out_size) {
    const float* x     = (const float*)d_in[0];
    const float* Wfc   = (const float*)d_in[1];
    const float* bfc   = (const float*)d_in[2];
    const float* gamma = (const float*)d_in[3];
    const float* beta  = (const float*)d_in[4];
    float* out = (float*)d_out;

    void* sq_ptr = nullptr;
    cudaGetSymbolAddress(&sq_ptr, g_sq);
    cudaMemsetAsync(sq_ptr, 0, BB * NN * sizeof(float));

    cudaFuncSetAttribute(gemm_y_mma, cudaFuncAttributeMaxDynamicSharedMemorySize, YS_TOTAL);
    cudaFuncSetAttribute(gemm_H_mma, cudaFuncAttributeMaxDynamicSharedMemorySize, HS_TOTAL);

    dim3 tb(32, 8);
    wprep_kernel<<<16, 1024>>>(Wfc);
    transpose_kernel<<<dim3(CC / 32, NN / 32, BB), tb>>>(x);
    gemm_y_mma<<<dim3(NN / 128, BB), 256, YS_TOTAL>>>(bfc);
    gemm_H_mma<<<dim3(528, BB), 256, HS_TOTAL>>>();
    agg_kernel<0><<<dim3(NN, BB), 128>>>();
    agg_kernel<1><<<dim3(NN, BB), 128>>>();
    stats_p1<<<64, 256>>>();
    stats_p2<<<1, 128>>>();
    out_kernel<<<dim3(NN / 32, CC / 32, BB), tb>>>(gamma, beta, out);
}